// round 8
// baseline (speedup 1.0000x reference)
#include <cuda_runtime.h>

typedef unsigned long long u64;
typedef unsigned int u32;

#define DD 1024
#define BB 64
#define BETA_W 0.001f

__device__ __forceinline__ u64 ce_sel(u64 a, u64 b, bool takeMax) {
    return takeMax ? (a > b ? a : b) : (a < b ? a : b);
}

__global__ __launch_bounds__(1024) void oscarmax_kernel(const float* __restrict__ x,
                                                        float* __restrict__ out) {
    __shared__ u64   sbuf[2][DD];      // sort buffers; after: bnd (int[1024]) | cstk (float2[1024])
    __shared__ float sy[DD];           // s values
    __shared__ float CS[DD + 1];       // prefix sums of s
    __shared__ float mval[DD];         // pool value at block-start positions
    __shared__ float sgn_mark[DD];     // sign(x); then markerpos (int view)
    __shared__ float zcs[DD];          // sorted z, then cumsum
    __shared__ int   cntA[32];
    __shared__ int   cntB[32];
    __shared__ int   part_b[32];       // fill max-scan
    __shared__ int   part_c[32];       // rank scan
    __shared__ float part_d[32];       // CS scan + cumsum scan (barrier-separated)

    int*    markerpos = (int*)sgn_mark;
    int*    bnd  = (int*)&sbuf[0][0];      // boundary positions
    float2* cstk = (float2*)&sbuf[1][0];   // per-chunk PAVA stacks

    const int lane = threadIdx.x & 31;
    const int wrp  = threadIdx.x >> 5;
    const int tid  = threadIdx.x;
    const int row  = blockIdx.x;
    const unsigned FULL = 0xffffffffu;

    // ---- load, sign, pack sortable u64 (|x| desc, idx asc tiebreak) ----
    float xv = x[row * DD + tid];
    sgn_mark[tid] = (xv > 0.0f) ? 1.0f : ((xv < 0.0f) ? -1.0f : 0.0f);
    u32 kb = __float_as_uint(fabsf(xv));
    u64 v = ((u64)kb << 32) | (u32)(~(u32)tid);

    // ---- bitonic sort (descending) ----
    #pragma unroll
    for (int k = 2; k <= 32; k <<= 1) {
        #pragma unroll
        for (int j = k >> 1; j > 0; j >>= 1) {
            u64 o = __shfl_xor_sync(FULL, v, j);
            bool lower = ((tid & j) == 0);
            bool dec   = ((tid & k) == 0);
            v = ce_sel(v, o, lower == dec);
        }
    }
    int cur = 0;
    sbuf[0][tid] = v;
    __syncthreads();
    #pragma unroll 1
    for (int k = 64; k <= 1024; k <<= 1) {
        #pragma unroll 1
        for (int j = k >> 1; j >= 32; j >>= 1) {
            u64 o = sbuf[cur][tid ^ j];
            bool lower = ((tid & j) == 0);
            bool dec   = ((tid & k) == 0);
            v = ce_sel(v, o, lower == dec);
            sbuf[cur ^ 1][tid] = v;
            __syncthreads();
            cur ^= 1;
        }
        #pragma unroll
        for (int j = 16; j > 0; j >>= 1) {
            u64 o = __shfl_xor_sync(FULL, v, j);
            bool lower = ((tid & j) == 0);
            bool dec   = ((tid & k) == 0);
            v = ce_sel(v, o, lower == dec);
        }
        if (k < 1024) {
            sbuf[cur ^ 1][tid] = v;
            __syncthreads();
            cur ^= 1;
        }
    }

    // ---- unpack, gather sign, write s ----
    float keyf  = __uint_as_float((u32)(v >> 32));
    int   idx   = (int)(~((u32)v));
    float sgn_i = sgn_mark[idx];            // all sgn reads complete before next sync
    float sval  = keyf - BETA_W * (float)(DD - 1 - tid);
    sy[tid] = sval;
    __syncthreads();     // sy visible; sort buffers dead -> bnd / cstk

    // ---- CS = prefix sums of s (inclusive scan from register) ----
    {
        float c = sval;
        #pragma unroll
        for (int o = 1; o < 32; o <<= 1) {
            float t = __shfl_up_sync(FULL, c, o);
            if (lane >= o) c += t;
        }
        if (lane == 31) part_d[wrp] = c;
        __syncthreads();
        if (tid < 32) {
            float p = part_d[tid];
            #pragma unroll
            for (int o = 1; o < 32; o <<= 1) {
                float t = __shfl_up_sync(FULL, p, o);
                if (tid >= o) p += t;
            }
            part_d[tid] = p;
        }
        __syncthreads();
        if (wrp > 0) c += part_d[wrp - 1];
        CS[tid + 1] = c;
        if (tid == 0) CS[0] = 0.0f;
    }

    // ---- level 1: per-chunk PAVA (32 chunks x 32 elems), lane 0 of each warp ----
    if (lane == 0) {
        const int base = wrp << 5;
        float2* cb = cstk + base;
        int nbk = 0;
        float ts = sy[base], tc = 1.0f;
        #pragma unroll 1
        for (int i = 1; i < 32; i++) {
            float cs = sy[base + i], cc = 1.0f;
            for (;;) {
                if (cs * tc > ts * cc) {
                    cs += ts; cc += tc;
                    if (nbk > 0) { --nbk; ts = cb[nbk].x; tc = cb[nbk].y; }
                    else         { ts = cs; tc = cc; goto nexti; }
                } else break;
            }
            cb[nbk++] = make_float2(ts, tc);
            ts = cs; tc = cc;
            nexti: ;
        }
        // emit boundary positions: blocks cb[0..nbk-1] then top block
        int pos = base;
        int* bb = bnd + base;
        #pragma unroll 1
        for (int b = 0; b < nbk; b++) { bb[b] = pos; pos += (int)cb[b].y; }
        bb[nbk] = pos;
        cntA[wrp] = nbk + 1;
    }
    markerpos[tid] = -1;        // repurpose sgn_mark (all sgn reads done pre-sync)
    __syncthreads();            // CS + chunk boundaries + markers visible

    // ---- merge tree: 5 levels of warp-cooperative tangent merges ----
    {
        int* cp = cntA;
        int* cn = cntB;
        #pragma unroll 1
        for (int L = 0; L < 5; L++) {
            int npairs = 16 >> L;
            if (wrp < npairs) {
                int childlen = 32 << L;
                int offA = wrp * 2 * childlen;
                int offB = offA + childlen;
                int segend = offA + 2 * childlen;
                int na = cp[2 * wrp];
                int nb = cp[2 * wrp + 1];
                // junction J = offB (right segment start). violation?
                int lastL = bnd[offA + na - 1];
                int nextR = (nb > 1) ? bnd[offB + 1] : segend;
                // slope(lastL,J) < slope(J,nextR) ?
                float sl1 = (CS[offB] - CS[lastL]) * (float)(nextR - offB);
                float sl2 = (CS[nextR] - CS[offB]) * (float)(offB - lastL);
                int cnt_new;
                if (sl1 >= sl2) {
                    // no violation: merged = LB ++ RB (copy RB to offA+na)
                    int npass = (nb + 31) >> 5;
                    for (int ps = 0; ps < npass; ps++) {
                        int p = (ps << 5) + lane;
                        int vq = (p < nb) ? bnd[offB + p] : 0;
                        __syncwarp();
                        if (p < nb) bnd[offA + na + p] = vq;
                        __syncwarp();
                    }
                    cnt_new = na + nb;
                } else {
                    // alternating tangent ballot searches
                    int lo = na - 1;
                    int hi = 1;
                    for (;;) {
                        int E = (hi < nb) ? bnd[offB + hi] : segend;
                        float csE = CS[E];
                        // LEFT: largest j in [1..lo] with slope(LB[j-1],LB[j]) >= slope(LB[j],E); else 0
                        int newlo = 0;
                        for (int w0 = lo; w0 >= 1; w0 -= 32) {
                            int j = w0 - lane;
                            bool pr = false;
                            if (j >= 1) {
                                int a = bnd[offA + j - 1];
                                int b = bnd[offA + j];
                                pr = (CS[b] - CS[a]) * (float)(E - b) >=
                                     (csE - CS[b]) * (float)(b - a);
                            }
                            unsigned m = __ballot_sync(FULL, pr);
                            if (m) { newlo = w0 - (__ffs(m) - 1); break; }
                        }
                        int Lpos = bnd[offA + newlo];
                        float csL = CS[Lpos];
                        // RIGHT: smallest i in [hi..nb-1] with slope(RB[i],next) <= slope(Lpos,RB[i]); else nb
                        int newhi = nb;
                        for (int w0 = hi; w0 < nb; w0 += 32) {
                            int i = w0 + lane;
                            bool pr = false;
                            if (i < nb) {
                                int b = bnd[offB + i];
                                int cpos = (i + 1 < nb) ? bnd[offB + i + 1] : segend;
                                pr = (CS[cpos] - CS[b]) * (float)(b - Lpos) <=
                                     (CS[b] - csL) * (float)(cpos - b);
                            }
                            unsigned m = __ballot_sync(FULL, pr);
                            if (m) { newhi = w0 + (__ffs(m) - 1); break; }
                        }
                        if (newlo == lo && newhi == hi) break;
                        lo = newlo; hi = newhi;
                    }
                    // keep LB[0..lo] ++ RB[hi..nb-1]
                    int keepR = nb - hi;
                    int npass = (keepR + 31) >> 5;
                    for (int ps = 0; ps < npass; ps++) {
                        int p = (ps << 5) + lane;
                        int vq = (p < keepR) ? bnd[offB + hi + p] : 0;
                        __syncwarp();
                        if (p < keepR) bnd[offA + lo + 1 + p] = vq;
                        __syncwarp();
                    }
                    cnt_new = lo + 1 + keepR;
                }
                if (lane == 0) cn[wrp] = cnt_new;
            }
            __syncthreads();
            int* t = cp; cp = cn; cn = t;
        }

        // ---- direct expansion from boundaries + CS ----
        int nf = cp[0];
        if (tid < nf) {
            int p   = bnd[tid];
            int nxt = (tid + 1 < nf) ? bnd[tid + 1] : DD;
            float mean = (CS[nxt] - CS[p]) / (float)(nxt - p);
            mval[p] = fmaxf(mean, 0.0f);
            markerpos[p] = p;
        }
    }
    __syncthreads();

    // ---- fill-forward: block inclusive max-scan of markerpos ----
    int mp = markerpos[tid];
    #pragma unroll
    for (int o = 1; o < 32; o <<= 1) {
        int t = __shfl_up_sync(FULL, mp, o);
        if (lane >= o) mp = max(mp, t);
    }
    if (lane == 31) part_b[wrp] = mp;
    __syncthreads();
    if (tid < 32) {
        int p = part_b[tid];
        #pragma unroll
        for (int o = 1; o < 32; o <<= 1) {
            int t = __shfl_up_sync(FULL, p, o);
            if (tid >= o) p = max(p, t);
        }
        part_b[tid] = p;
    }
    __syncthreads();
    if (wrp > 0) mp = max(mp, part_b[wrp - 1]);

    float y = mval[mp];            // pooled mean, clamped >= 0, nonincreasing in tid
    float z = sgn_i * y;           // oscar prox at sorted position tid

    // ---- sorted-z without a sort: packed (P,N) rank scan ----
    int fP = (z > 0.0f) ? 1 : 0;
    int fN = (z < 0.0f) ? 1 : 0;
    int pk = (fP << 16) | fN;
    int incl = pk;
    #pragma unroll
    for (int o = 1; o < 32; o <<= 1) {
        int t = __shfl_up_sync(FULL, incl, o);
        if (lane >= o) incl += t;
    }
    if (lane == 31) part_c[wrp] = incl;
    __syncthreads();
    if (tid < 32) {
        int p = part_c[tid];
        #pragma unroll
        for (int o = 1; o < 32; o <<= 1) {
            int t = __shfl_up_sync(FULL, p, o);
            if (tid >= o) p += t;
        }
        part_c[tid] = p;
    }
    __syncthreads();
    if (wrp > 0) incl += part_c[wrp - 1];
    int excl = incl - pk;
    int totalP = __syncthreads_count(z > 0.0f);   // barrier + block-wide count

    int pPex = excl >> 16;
    int pNex = excl & 0xffff;
    int pos;
    if (z > 0.0f)      pos = pPex;                          // positives: i-order
    else if (z < 0.0f) pos = DD - 1 - pNex;                 // negatives: reverse i-order
    else               pos = totalP + (tid - pPex - pNex);  // zeros: middle
    zcs[pos] = z;
    __syncthreads();

    // ---- sparsemax: cumsum, support count, tau ----
    float zs_t = zcs[tid];
    float c2 = zs_t;
    #pragma unroll
    for (int o = 1; o < 32; o <<= 1) {
        float t = __shfl_up_sync(FULL, c2, o);
        if (lane >= o) c2 += t;
    }
    if (lane == 31) part_d[wrp] = c2;
    __syncthreads();
    if (tid < 32) {
        float p = part_d[tid];
        #pragma unroll
        for (int o = 1; o < 32; o <<= 1) {
            float t = __shfl_up_sync(FULL, p, o);
            if (tid >= o) p += t;
        }
        part_d[tid] = p;
    }
    __syncthreads();
    if (wrp > 0) c2 += part_d[wrp - 1];

    zcs[tid] = c2;
    bool flagS = (1.0f + (float)(tid + 1) * zs_t) > c2;
    int k_sup = __syncthreads_count(flagS);   // support is a prefix; also the barrier
    float tau = (zcs[k_sup - 1] - 1.0f) / (float)k_sup;

    out[row * DD + idx] = fmaxf(z - tau, 0.0f);
}

extern "C" void kernel_launch(void* const* d_in, const int* in_sizes, int n_in,
                              void* d_out, int out_size) {
    const float* x = (const float*)d_in[0];
    float* out = (float*)d_out;
    oscarmax_kernel<<<BB, DD>>>(x, out);
}

// round 9
// speedup vs baseline: 1.0892x; 1.0892x over previous
#include <cuda_runtime.h>

typedef unsigned long long u64;
typedef unsigned int u32;

#define DD 1024
#define BB 64
#define BETA_W 0.001f

__device__ __forceinline__ u64 ce_sel(u64 a, u64 b, bool takeMax) {
    return takeMax ? (a > b ? a : b) : (a < b ? a : b);
}

// Junction cascade over a gapped block array with edge pointers (R6).
__device__ void cascade(float2* b, int* jl, int* jr, int ls, int junc, int re) {
    int li = junc - 1;
    float2 L = b[li];
    if (L.y == 0.0f) { li = jl[li]; L = b[li]; }
    float2 P = b[junc];
    if (!(L.x * P.y < P.x * L.y)) return;
    P.x += L.x; P.y += L.y;
    b[li].y = 0.0f;
    b[junc].y = 0.0f;
    int lpos = li;
    int lc = li - 1;
    int rc = junc + 1;
    int lstop = ls - 1;
    int rstop = re;
    bool changed = true;
    while (changed) {
        changed = false;
        while (lc >= ls) {
            float2 Lb = b[lc];
            if (Lb.y == 0.0f) { lc = jl[lc]; if (lc < ls) break; Lb = b[lc]; }
            if (Lb.x * P.y < P.x * Lb.y) {
                P.x += Lb.x; P.y += Lb.y;
                b[lc].y = 0.0f;
                lpos = lc; --lc; changed = true;
            } else { lstop = lc; break; }
        }
        while (rc < re) {
            float2 Rb = b[rc];
            if (Rb.y == 0.0f) { rc = jr[rc]; if (rc >= re) break; Rb = b[rc]; }
            if (Rb.x * P.y > P.x * Rb.y) {
                P.x += Rb.x; P.y += Rb.y;
                b[rc].y = 0.0f;
                ++rc; changed = true;
            } else { rstop = rc; break; }
        }
    }
    b[lpos] = P;
    if (lpos - 1 > lstop) { jl[lpos - 1] = lstop; jr[lstop + 1] = lpos; }
    if (rstop - 1 > lpos) { jl[rstop - 1] = lpos; jr[lpos + 1] = rstop; }
}

__global__ __launch_bounds__(1024) void oscarmax_kernel(const float* __restrict__ x,
                                                        float* __restrict__ out) {
    __shared__ u64   sbuf[2][DD];      // sort buffers; after: bA (sbuf[0]) | jl/jr (sbuf[1])
    __shared__ float mval[DD];         // pool value at block-start positions
    __shared__ float sgn_mark[DD];     // sign(x); then markerpos (int view)
    __shared__ int   part_a[32];       // expansion scan
    __shared__ int   part_b[32];       // fill max-scan
    __shared__ int   part_c[32];       // rank scan
    __shared__ float part_p[32];       // positive-sum scan
    __shared__ float part_n[32];       // negative-sum scan
    __shared__ float tau_sh;

    int*    markerpos = (int*)sgn_mark;
    float2* bA = (float2*)&sbuf[0][0];
    int*    jl = (int*)&sbuf[1][0];
    int*    jr = jl + DD;

    const int tid  = threadIdx.x;
    const int lane = tid & 31;
    const int wrp  = tid >> 5;
    const int row  = blockIdx.x;
    const unsigned FULL = 0xffffffffu;

    // ---- load, sign, pack sortable u64 (|x| desc, idx asc tiebreak) ----
    float xv = x[row * DD + tid];
    sgn_mark[tid] = (xv > 0.0f) ? 1.0f : ((xv < 0.0f) ? -1.0f : 0.0f);
    u32 kb = __float_as_uint(fabsf(xv));
    u64 v = ((u64)kb << 32) | (u32)(~(u32)tid);

    // ---- bitonic sort (descending) ----
    #pragma unroll
    for (int k = 2; k <= 32; k <<= 1) {
        #pragma unroll
        for (int j = k >> 1; j > 0; j >>= 1) {
            u64 o = __shfl_xor_sync(FULL, v, j);
            bool lower = ((tid & j) == 0);
            bool dec   = ((tid & k) == 0);
            v = ce_sel(v, o, lower == dec);
        }
    }
    int cur = 0;
    sbuf[0][tid] = v;
    __syncthreads();
    #pragma unroll 1
    for (int k = 64; k <= 1024; k <<= 1) {
        #pragma unroll 1
        for (int j = k >> 1; j >= 32; j >>= 1) {
            u64 o = sbuf[cur][tid ^ j];
            bool lower = ((tid & j) == 0);
            bool dec   = ((tid & k) == 0);
            v = ce_sel(v, o, lower == dec);
            sbuf[cur ^ 1][tid] = v;
            __syncthreads();
            cur ^= 1;
        }
        #pragma unroll
        for (int j = 16; j > 0; j >>= 1) {
            u64 o = __shfl_xor_sync(FULL, v, j);
            bool lower = ((tid & j) == 0);
            bool dec   = ((tid & k) == 0);
            v = ce_sel(v, o, lower == dec);
        }
        if (k < 1024) {
            sbuf[cur ^ 1][tid] = v;
            __syncthreads();
            cur ^= 1;
        }
    }

    // ---- unpack, gather sign; s stays in a register ----
    float keyf  = __uint_as_float((u32)(v >> 32));
    int   idx   = (int)(~((u32)v));
    float sgn_i = sgn_mark[idx];
    float sval  = keyf - BETA_W * (float)(DD - 1 - tid);
    __syncthreads();     // all sgn gathers done; sort buffers dead -> bA / jl / jr

    markerpos[tid] = -1; // repurpose sgn_mark

    // ---- per-chunk PAVA: every warp runs its chunk, all lanes redundantly via shfl ----
    {
        const int base = wrp << 5;
        float2* cb = bA + base;
        int nb = 0;
        float ts = __shfl_sync(FULL, sval, 0), tc = 1.0f;
        #pragma unroll 1
        for (int i = 1; i < 32; i++) {
            float cs = __shfl_sync(FULL, sval, i), cc = 1.0f;
            for (;;) {
                if (cs * tc > ts * cc) {           // cur_mean > top_mean
                    cs += ts; cc += tc;
                    if (nb > 0) { --nb; float2 t = cb[nb]; ts = t.x; tc = t.y; }
                    else        { ts = cs; tc = cc; goto nexti; }
                } else break;
            }
            cb[nb++] = make_float2(ts, tc);        // all lanes: same value, same addr
            ts = cs; tc = cc;
            nexti: ;
        }
        cb[nb++] = make_float2(ts, tc);
        if (lane >= nb) cb[lane].y = 0.0f;         // parallel dead-slot cleanup
        if (nb < 32 && lane == 0) {
            jl[base + 31] = base + nb - 1;
            jr[base + nb] = base + 32;
        }
    }
    __syncthreads();     // bA, jl/jr, markerpos visible

    // ---- merge tree: 5 levels, one cascade per WARP (no intra-warp serialization) ----
    #pragma unroll 1
    for (int L = 0; L < 5; L++) {
        int npairs = 16 >> L;
        if (lane == 0 && wrp < npairs) {
            int seg = 64 << L;
            int ls  = wrp * seg;
            cascade(bA, jl, jr, ls, ls + (seg >> 1), ls + seg);
        }
        __syncthreads();
    }

    // ---- expansion: block exclusive scan of block counts ----
    {
        float2 bfin = bA[tid];
        int cnt = (int)bfin.y;
        int inc = cnt;
        #pragma unroll
        for (int o = 1; o < 32; o <<= 1) {
            int t = __shfl_up_sync(FULL, inc, o);
            if (lane >= o) inc += t;
        }
        if (lane == 31) part_a[wrp] = inc;
        __syncthreads();
        if (tid < 32) {
            int p = part_a[tid];
            #pragma unroll
            for (int o = 1; o < 32; o <<= 1) {
                int t = __shfl_up_sync(FULL, p, o);
                if (tid >= o) p += t;
            }
            part_a[tid] = p;
        }
        __syncthreads();
        if (wrp > 0) inc += part_a[wrp - 1];
        int start = inc - cnt;
        if (cnt > 0) {
            mval[start] = fmaxf(bfin.x / bfin.y, 0.0f);
            markerpos[start] = start;
        }
    }
    __syncthreads();

    // ---- fill-forward: block inclusive max-scan of markerpos ----
    int mp = markerpos[tid];
    #pragma unroll
    for (int o = 1; o < 32; o <<= 1) {
        int t = __shfl_up_sync(FULL, mp, o);
        if (lane >= o) mp = max(mp, t);
    }
    if (lane == 31) part_b[wrp] = mp;
    __syncthreads();
    if (tid < 32) {
        int p = part_b[tid];
        #pragma unroll
        for (int o = 1; o < 32; o <<= 1) {
            int t = __shfl_up_sync(FULL, p, o);
            if (tid >= o) p = max(p, t);
        }
        part_b[tid] = p;
    }
    __syncthreads();
    if (wrp > 0) mp = max(mp, part_b[wrp - 1]);

    float y = mval[mp];            // pooled mean, clamped >= 0, nonincreasing in tid
    float z = sgn_i * y;           // oscar prox at sorted position tid

    // ---- fused epilogue: one combined scan gives rank AND sorted-cumsum ----
    {
        int fP = (z > 0.0f) ? 1 : 0;
        int fN = (z < 0.0f) ? 1 : 0;
        int   pk = (fP << 16) | fN;
        float zp = fP ? z : 0.0f;
        float zn = fN ? z : 0.0f;
        int   ipk = pk;
        float izp = zp, izn = zn;
        #pragma unroll
        for (int o = 1; o < 32; o <<= 1) {
            int   ti = __shfl_up_sync(FULL, ipk, o);
            float tp = __shfl_up_sync(FULL, izp, o);
            float tn = __shfl_up_sync(FULL, izn, o);
            if (lane >= o) { ipk += ti; izp += tp; izn += tn; }
        }
        if (lane == 31) { part_c[wrp] = ipk; part_p[wrp] = izp; part_n[wrp] = izn; }
        __syncthreads();
        if (tid < 32) {
            int   p  = part_c[tid];
            float pp = part_p[tid];
            float pn = part_n[tid];
            #pragma unroll
            for (int o = 1; o < 32; o <<= 1) {
                int   ti = __shfl_up_sync(FULL, p,  o);
                float tp = __shfl_up_sync(FULL, pp, o);
                float tn = __shfl_up_sync(FULL, pn, o);
                if (tid >= o) { p += ti; pp += tp; pn += tn; }
            }
            part_c[tid] = p; part_p[tid] = pp; part_n[tid] = pn;
        }
        __syncthreads();
        if (wrp > 0) {
            ipk += part_c[wrp - 1];
            izp += part_p[wrp - 1];
            izn += part_n[wrp - 1];
        }
        int   total = part_c[31];
        float totP  = part_p[31];
        float totN  = part_n[31];

        int excl = ipk - pk;
        int pPex = excl >> 16;
        int pNex = excl & 0xffff;
        int totalPcnt = total >> 16;

        int pos;
        float c;
        if (z > 0.0f)      { pos = pPex;                          c = izp; }
        else if (z < 0.0f) { pos = DD - 1 - pNex;                 c = (totP + totN) - (izn - zn); }
        else               { pos = totalPcnt + (tid - pPex - pNex); c = totP; }

        bool flag = (1.0f + (float)(pos + 1) * z) > c;
        int k_sup = __syncthreads_count(flag);        // support is a prefix in sorted order
        if (pos == k_sup - 1) tau_sh = (c - 1.0f) / (float)k_sup;
        __syncthreads();

        out[row * DD + idx] = fmaxf(z - tau_sh, 0.0f);
    }
}

extern "C" void kernel_launch(void* const* d_in, const int* in_sizes, int n_in,
                              void* d_out, int out_size) {
    const float* x = (const float*)d_in[0];
    float* out = (float*)d_out;
    oscarmax_kernel<<<BB, DD>>>(x, out);
}

// round 10
// speedup vs baseline: 1.1758x; 1.0795x over previous
#include <cuda_runtime.h>

typedef unsigned long long u64;
typedef unsigned int u32;

#define DD 1024
#define BB 64
#define BETA_W 0.001f

__device__ __forceinline__ u64 ce_sel(u64 a, u64 b, bool takeMax) {
    return takeMax ? (a > b ? a : b) : (a < b ? a : b);
}

// Junction cascade over a gapped, position-indexed block array with edge pointers.
// Slot p valid (cnt>0) <=> a block starts at element-position p.
__device__ void cascade(float2* b, int* jl, int* jr, int ls, int junc, int re) {
    int li = junc - 1;
    float2 L = b[li];
    if (L.y == 0.0f) { li = jl[li]; L = b[li]; }
    float2 P = b[junc];
    if (!(L.x * P.y < P.x * L.y)) return;
    P.x += L.x; P.y += L.y;
    b[li].y = 0.0f;
    b[junc].y = 0.0f;
    int lpos = li;
    int lc = li - 1;
    int rc = junc + 1;
    int lstop = ls - 1;
    int rstop = re;
    bool changed = true;
    while (changed) {
        changed = false;
        while (lc >= ls) {
            float2 Lb = b[lc];
            if (Lb.y == 0.0f) { lc = jl[lc]; if (lc < ls) break; Lb = b[lc]; }
            if (Lb.x * P.y < P.x * Lb.y) {
                P.x += Lb.x; P.y += Lb.y;
                b[lc].y = 0.0f;
                lpos = lc; --lc; changed = true;
            } else { lstop = lc; break; }
        }
        while (rc < re) {
            float2 Rb = b[rc];
            if (Rb.y == 0.0f) { rc = jr[rc]; if (rc >= re) break; Rb = b[rc]; }
            if (Rb.x * P.y > P.x * Rb.y) {
                P.x += Rb.x; P.y += Rb.y;
                b[rc].y = 0.0f;
                ++rc; changed = true;
            } else { rstop = rc; break; }
        }
    }
    b[lpos] = P;
    if (lpos - 1 > lstop) { jl[lpos - 1] = lstop; jr[lstop + 1] = lpos; }
    if (rstop - 1 > lpos) { jl[rstop - 1] = lpos; jr[lpos + 1] = rstop; }
}

__global__ __launch_bounds__(1024) void oscarmax_kernel(const float* __restrict__ x,
                                                        float* __restrict__ out) {
    __shared__ u64   sbuf[2][DD];      // sort buffers; after: bA (sbuf[0]) | jl/jr (sbuf[1])
    __shared__ int   part_b[32];       // fill max-scan
    __shared__ int   part_c[32];       // rank scan
    __shared__ float part_p[32];       // positive-sum scan
    __shared__ float part_n[32];       // negative-sum scan
    __shared__ float tau_sh;

    float2* bA = (float2*)&sbuf[0][0];
    int*    jl = (int*)&sbuf[1][0];
    int*    jr = jl + DD;

    const int tid  = threadIdx.x;
    const int lane = tid & 31;
    const int wrp  = tid >> 5;
    const int row  = blockIdx.x;
    const unsigned FULL = 0xffffffffu;

    // ---- load, pack sortable u64: key=|x| bits (desc), payload=(idx<<1)|negbit ----
    float xv = x[row * DD + tid];
    u32 kb = __float_as_uint(fabsf(xv));
    u32 pl = ((u32)tid << 1) | (xv < 0.0f ? 1u : 0u);
    u64 v = ((u64)kb << 32) | pl;

    // ---- bitonic sort (descending) ----
    #pragma unroll
    for (int k = 2; k <= 32; k <<= 1) {
        #pragma unroll
        for (int j = k >> 1; j > 0; j >>= 1) {
            u64 o = __shfl_xor_sync(FULL, v, j);
            bool lower = ((tid & j) == 0);
            bool dec   = ((tid & k) == 0);
            v = ce_sel(v, o, lower == dec);
        }
    }
    int cur = 0;
    sbuf[0][tid] = v;
    __syncthreads();
    #pragma unroll 1
    for (int k = 64; k <= 1024; k <<= 1) {
        #pragma unroll 1
        for (int j = k >> 1; j >= 32; j >>= 1) {
            u64 o = sbuf[cur][tid ^ j];
            bool lower = ((tid & j) == 0);
            bool dec   = ((tid & k) == 0);
            v = ce_sel(v, o, lower == dec);
            sbuf[cur ^ 1][tid] = v;
            __syncthreads();
            cur ^= 1;
        }
        #pragma unroll
        for (int j = 16; j > 0; j >>= 1) {
            u64 o = __shfl_xor_sync(FULL, v, j);
            bool lower = ((tid & j) == 0);
            bool dec   = ((tid & k) == 0);
            v = ce_sel(v, o, lower == dec);
        }
        if (k < 1024) {
            sbuf[cur ^ 1][tid] = v;
            __syncthreads();
            cur ^= 1;
        }
    }

    // ---- unpack: key, index, sign all from the sorted word ----
    float keyf  = __uint_as_float((u32)(v >> 32));
    u32   plo   = (u32)v;
    int   idx   = (int)(plo >> 1);
    float sgn_i = (plo & 1u) ? -1.0f : 1.0f;
    float sval  = keyf - BETA_W * (float)(DD - 1 - tid);
    __syncthreads();     // all cross-warp sort reads done; sbuf dead -> bA / jl / jr

    // ---- per-chunk PAVA: register stack (lane-indexed, shfl-accessed), all lanes lockstep ----
    {
        const int base = wrp << 5;
        bA[base + lane] = make_float2(0.0f, 0.0f);      // clear chunk slots
        __syncwarp();

        float psum = 0.0f, pcnt = 0.0f;                 // stack entry owned by this lane
        int   ppos = 0;
        int nb = 0;
        float ts = __shfl_sync(FULL, sval, 0), tc = 1.0f;
        int tpos = 0;
        #pragma unroll 1
        for (int i = 1; i < 32; i++) {
            float cs = __shfl_sync(FULL, sval, i), cc = 1.0f;
            int cpos = i;
            for (;;) {
                if (cs * tc > ts * cc) {                // cur_mean > top_mean: pool
                    cs += ts; cc += tc; cpos = tpos;
                    if (nb > 0) {
                        --nb;
                        ts   = __shfl_sync(FULL, psum, nb);
                        tc   = __shfl_sync(FULL, pcnt, nb);
                        tpos = __shfl_sync(FULL, ppos, nb);
                    } else { ts = cs; tc = cc; tpos = cpos; goto nexti; }
                } else break;
            }
            if (lane == nb) { psum = ts; pcnt = tc; ppos = tpos; }
            nb++;
            ts = cs; tc = cc; tpos = cpos;
            nexti: ;
        }
        if (lane == nb) { psum = ts; pcnt = tc; ppos = tpos; }
        nb++;

        // parallel emit: block b at slot base+start; gap edges for cnt>1
        if (lane < nb) {
            int st = base + ppos;
            int c  = (int)pcnt;
            bA[st] = make_float2(psum, pcnt);
            if (c > 1) {
                jr[st + 1]     = st + c;
                jl[st + c - 1] = st;
            }
        }
    }
    __syncthreads();     // bA, jl/jr visible

    // ---- merge tree: 5 levels, one cascade per WARP ----
    #pragma unroll 1
    for (int L = 0; L < 5; L++) {
        int npairs = 16 >> L;
        if (lane == 0 && wrp < npairs) {
            int seg = 64 << L;
            int ls  = wrp * seg;
            cascade(bA, jl, jr, ls, ls + (seg >> 1), ls + seg);
        }
        __syncthreads();
    }

    // ---- fill-forward: valid slot index max-scan gives each position its block start ----
    float2 bme = bA[tid];
    int mp = (bme.y > 0.0f) ? tid : -1;
    #pragma unroll
    for (int o = 1; o < 32; o <<= 1) {
        int t = __shfl_up_sync(FULL, mp, o);
        if (lane >= o) mp = max(mp, t);
    }
    if (lane == 31) part_b[wrp] = mp;
    __syncthreads();
    if (tid < 32) {
        int p = part_b[tid];
        #pragma unroll
        for (int o = 1; o < 32; o <<= 1) {
            int t = __shfl_up_sync(FULL, p, o);
            if (tid >= o) p = max(p, t);
        }
        part_b[tid] = p;
    }
    __syncthreads();
    if (wrp > 0) mp = max(mp, part_b[wrp - 1]);

    float2 blk = bA[mp];                       // block containing position tid
    float y = fmaxf(blk.x / blk.y, 0.0f);      // pooled mean, clamped; nonincreasing in tid
    float z = sgn_i * y;                       // oscar prox at sorted position tid

    // ---- fused epilogue: one combined scan -> rank AND sorted cumsum ----
    {
        int fP = (z > 0.0f) ? 1 : 0;
        int fN = (z < 0.0f) ? 1 : 0;
        int   pk = (fP << 16) | fN;
        float zp = fP ? z : 0.0f;
        float zn = fN ? z : 0.0f;
        int   ipk = pk;
        float izp = zp, izn = zn;
        #pragma unroll
        for (int o = 1; o < 32; o <<= 1) {
            int   ti = __shfl_up_sync(FULL, ipk, o);
            float tp = __shfl_up_sync(FULL, izp, o);
            float tn = __shfl_up_sync(FULL, izn, o);
            if (lane >= o) { ipk += ti; izp += tp; izn += tn; }
        }
        if (lane == 31) { part_c[wrp] = ipk; part_p[wrp] = izp; part_n[wrp] = izn; }
        __syncthreads();
        if (tid < 32) {
            int   p  = part_c[tid];
            float pp = part_p[tid];
            float pn = part_n[tid];
            #pragma unroll
            for (int o = 1; o < 32; o <<= 1) {
                int   ti = __shfl_up_sync(FULL, p,  o);
                float tp = __shfl_up_sync(FULL, pp, o);
                float tn = __shfl_up_sync(FULL, pn, o);
                if (tid >= o) { p += ti; pp += tp; pn += tn; }
            }
            part_c[tid] = p; part_p[tid] = pp; part_n[tid] = pn;
        }
        __syncthreads();
        if (wrp > 0) {
            ipk += part_c[wrp - 1];
            izp += part_p[wrp - 1];
            izn += part_n[wrp - 1];
        }
        int   total = part_c[31];
        float totP  = part_p[31];
        float totN  = part_n[31];

        int excl = ipk - pk;
        int pPex = excl >> 16;
        int pNex = excl & 0xffff;
        int totalPcnt = total >> 16;

        int pos;
        float c;
        if (z > 0.0f)      { pos = pPex;                            c = izp; }
        else if (z < 0.0f) { pos = DD - 1 - pNex;                   c = (totP + totN) - (izn - zn); }
        else               { pos = totalPcnt + (tid - pPex - pNex); c = totP; }

        bool flag = (1.0f + (float)(pos + 1) * z) > c;
        int k_sup = __syncthreads_count(flag);        // support is a prefix in sorted order
        if (pos == k_sup - 1) tau_sh = (c - 1.0f) / (float)k_sup;
        __syncthreads();

        out[row * DD + idx] = fmaxf(z - tau_sh, 0.0f);
    }
}

extern "C" void kernel_launch(void* const* d_in, const int* in_sizes, int n_in,
                              void* d_out, int out_size) {
    const float* x = (const float*)d_in[0];
    float* out = (float*)d_out;
    oscarmax_kernel<<<BB, DD>>>(x, out);
}

// round 11
// speedup vs baseline: 1.1867x; 1.0093x over previous
#include <cuda_runtime.h>

typedef unsigned long long u64;
typedef unsigned int u32;

#define DD 1024
#define BB 64
#define BETA_W 0.001f

__device__ __forceinline__ u64 ce_sel(u64 a, u64 b, bool takeMax) {
    return takeMax ? (a > b ? a : b) : (a < b ? a : b);
}

// intra-warp tail of bitonic stage k: j = 16..1 via shfl
__device__ __forceinline__ void intra_tail(u64& v, int tid, int k, unsigned FULL) {
    #pragma unroll
    for (int j = 16; j > 0; j >>= 1) {
        u64 o = __shfl_xor_sync(FULL, v, j);
        v = ce_sel(v, o, ((tid & j) == 0) == ((tid & k) == 0));
    }
}

// Junction cascade over a gapped, position-indexed block array with edge pointers.
__device__ void cascade(float2* b, int* jl, int* jr, int ls, int junc, int re) {
    int li = junc - 1;
    float2 L = b[li];
    if (L.y == 0.0f) { li = jl[li]; L = b[li]; }
    float2 P = b[junc];
    if (!(L.x * P.y < P.x * L.y)) return;
    P.x += L.x; P.y += L.y;
    b[li].y = 0.0f;
    b[junc].y = 0.0f;
    int lpos = li;
    int lc = li - 1;
    int rc = junc + 1;
    int lstop = ls - 1;
    int rstop = re;
    bool changed = true;
    while (changed) {
        changed = false;
        while (lc >= ls) {
            float2 Lb = b[lc];
            if (Lb.y == 0.0f) { lc = jl[lc]; if (lc < ls) break; Lb = b[lc]; }
            if (Lb.x * P.y < P.x * Lb.y) {
                P.x += Lb.x; P.y += Lb.y;
                b[lc].y = 0.0f;
                lpos = lc; --lc; changed = true;
            } else { lstop = lc; break; }
        }
        while (rc < re) {
            float2 Rb = b[rc];
            if (Rb.y == 0.0f) { rc = jr[rc]; if (rc >= re) break; Rb = b[rc]; }
            if (Rb.x * P.y > P.x * Rb.y) {
                P.x += Rb.x; P.y += Rb.y;
                b[rc].y = 0.0f;
                ++rc; changed = true;
            } else { rstop = rc; break; }
        }
    }
    b[lpos] = P;
    if (lpos - 1 > lstop) { jl[lpos - 1] = lstop; jr[lstop + 1] = lpos; }
    if (rstop - 1 > lpos) { jl[rstop - 1] = lpos; jr[lpos + 1] = rstop; }
}

__global__ __launch_bounds__(1024) void oscarmax_kernel(const float* __restrict__ x,
                                                        float* __restrict__ out) {
    __shared__ u64   sbuf[2][DD];      // sort buffers; after: bA (sbuf[0]) | jl/jr (sbuf[1])
    __shared__ int   part_b[32];       // fill max-scan
    __shared__ int   part_c[32];       // rank scan
    __shared__ float part_p[32];       // positive-sum scan
    __shared__ float part_n[32];       // negative-sum scan
    __shared__ float tau_sh;

    float2* bA = (float2*)&sbuf[0][0];
    int*    jl = (int*)&sbuf[1][0];
    int*    jr = jl + DD;
    u64*    b0 = &sbuf[0][0];
    u64*    b1 = &sbuf[1][0];

    const int tid  = threadIdx.x;
    const int lane = tid & 31;
    const int wrp  = tid >> 5;
    const int row  = blockIdx.x;
    const unsigned FULL = 0xffffffffu;

    // ---- load, pack sortable u64: key=|x| bits (desc), payload=(idx<<1)|negbit ----
    float xv = x[row * DD + tid];
    u32 kb = __float_as_uint(fabsf(xv));
    u32 pl = ((u32)tid << 1) | (xv < 0.0f ? 1u : 0u);
    u64 v = ((u64)kb << 32) | pl;

    // ---- bitonic sort (descending): k=2..32 pure shfl ----
    #pragma unroll
    for (int k = 2; k <= 32; k <<= 1) {
        #pragma unroll
        for (int j = k >> 1; j > 0; j >>= 1) {
            u64 o = __shfl_xor_sync(FULL, v, j);
            v = ce_sel(v, o, ((tid & j) == 0) == ((tid & k) == 0));
        }
    }

    // ---- fused cross-warp stages: 7 barriers total ----
    // k=64: [32]
    {
        const int k = 64;
        bool dec = ((tid & k) == 0);
        b0[tid] = v; __syncthreads();
        u64 o = b0[tid ^ 32];
        v = ce_sel(v, o, ((tid & 32) == 0) == dec);
        intra_tail(v, tid, k, FULL);
    }
    // k=128: [64,32] pair
    {
        const int k = 128;
        bool dec = ((tid & k) == 0);
        bool P1 = ((tid & 64) == 0) == dec;
        bool P2 = ((tid & 32) == 0) == dec;
        b1[tid] = v; __syncthreads();
        u64 a = ce_sel(v,            b1[tid ^ 64], P1);
        u64 b = ce_sel(b1[tid ^ 32], b1[tid ^ 96], P1);
        v = ce_sel(a, b, P2);
        intra_tail(v, tid, k, FULL);
    }
    // k=256: [128,64,32] triple
    {
        const int k = 256;
        bool dec = ((tid & k) == 0);
        bool P1 = ((tid & 128) == 0) == dec;
        bool P2 = ((tid & 64)  == 0) == dec;
        bool P3 = ((tid & 32)  == 0) == dec;
        b0[tid] = v; __syncthreads();
        u64 a = ce_sel(v,             b0[tid ^ 128], P1);
        u64 b = ce_sel(b0[tid ^ 64],  b0[tid ^ 192], P1);
        u64 c = ce_sel(a, b, P2);
        u64 d = ce_sel(b0[tid ^ 32],  b0[tid ^ 160], P1);
        u64 e = ce_sel(b0[tid ^ 96],  b0[tid ^ 224], P1);
        u64 f = ce_sel(d, e, P2);
        v = ce_sel(c, f, P3);
        intra_tail(v, tid, k, FULL);
    }
    // k=512: [256,128] + [64,32]
    {
        const int k = 512;
        bool dec = ((tid & k) == 0);
        {
            bool P1 = ((tid & 256) == 0) == dec;
            bool P2 = ((tid & 128) == 0) == dec;
            b1[tid] = v; __syncthreads();
            u64 a = ce_sel(v,             b1[tid ^ 256], P1);
            u64 b = ce_sel(b1[tid ^ 128], b1[tid ^ 384], P1);
            v = ce_sel(a, b, P2);
        }
        {
            bool P1 = ((tid & 64) == 0) == dec;
            bool P2 = ((tid & 32) == 0) == dec;
            b0[tid] = v; __syncthreads();
            u64 a = ce_sel(v,            b0[tid ^ 64], P1);
            u64 b = ce_sel(b0[tid ^ 32], b0[tid ^ 96], P1);
            v = ce_sel(a, b, P2);
        }
        intra_tail(v, tid, k, FULL);
    }
    // k=1024: [512,256,128] + [64,32]
    {
        const int k = 1024;
        const bool dec = true;   // (tid & 1024) == 0 always
        {
            bool P1 = ((tid & 512) == 0) == dec;
            bool P2 = ((tid & 256) == 0) == dec;
            bool P3 = ((tid & 128) == 0) == dec;
            b1[tid] = v; __syncthreads();
            u64 a = ce_sel(v,             b1[tid ^ 512], P1);
            u64 b = ce_sel(b1[tid ^ 256], b1[tid ^ 768], P1);
            u64 c = ce_sel(a, b, P2);
            u64 d = ce_sel(b1[tid ^ 128], b1[tid ^ 640], P1);
            u64 e = ce_sel(b1[tid ^ 384], b1[tid ^ 896], P1);
            u64 f = ce_sel(d, e, P2);
            v = ce_sel(c, f, P3);
        }
        {
            bool P1 = ((tid & 64) == 0) == dec;
            bool P2 = ((tid & 32) == 0) == dec;
            b0[tid] = v; __syncthreads();
            u64 a = ce_sel(v,            b0[tid ^ 64], P1);
            u64 b = ce_sel(b0[tid ^ 32], b0[tid ^ 96], P1);
            v = ce_sel(a, b, P2);
        }
        intra_tail(v, tid, k, FULL);
    }

    // ---- unpack: key, index, sign all from the sorted word ----
    float keyf  = __uint_as_float((u32)(v >> 32));
    u32   plo   = (u32)v;
    int   idx   = (int)(plo >> 1);
    float sgn_i = (plo & 1u) ? -1.0f : 1.0f;
    float sval  = keyf - BETA_W * (float)(DD - 1 - tid);
    __syncthreads();     // all cross-warp sort reads done; sbuf dead -> bA / jl / jr

    // ---- per-chunk PAVA: register stack (lane-indexed, shfl-accessed), lockstep ----
    {
        const int base = wrp << 5;
        bA[base + lane] = make_float2(0.0f, 0.0f);      // clear chunk slots
        __syncwarp();

        float psum = 0.0f, pcnt = 0.0f;                 // stack entry owned by this lane
        int   ppos = 0;
        int nb = 0;
        float ts = __shfl_sync(FULL, sval, 0), tc = 1.0f;
        int tpos = 0;
        #pragma unroll 1
        for (int i = 1; i < 32; i++) {
            float cs = __shfl_sync(FULL, sval, i), cc = 1.0f;
            int cpos = i;
            for (;;) {
                if (cs * tc > ts * cc) {                // cur_mean > top_mean: pool
                    cs += ts; cc += tc; cpos = tpos;
                    if (nb > 0) {
                        --nb;
                        ts   = __shfl_sync(FULL, psum, nb);
                        tc   = __shfl_sync(FULL, pcnt, nb);
                        tpos = __shfl_sync(FULL, ppos, nb);
                    } else { ts = cs; tc = cc; tpos = cpos; goto nexti; }
                } else break;
            }
            if (lane == nb) { psum = ts; pcnt = tc; ppos = tpos; }
            nb++;
            ts = cs; tc = cc; tpos = cpos;
            nexti: ;
        }
        if (lane == nb) { psum = ts; pcnt = tc; ppos = tpos; }
        nb++;

        if (lane < nb) {
            int st = base + ppos;
            int c  = (int)pcnt;
            bA[st] = make_float2(psum, pcnt);
            if (c > 1) {
                jr[st + 1]     = st + c;
                jl[st + c - 1] = st;
            }
        }
    }
    __syncthreads();     // bA, jl/jr visible

    // ---- merge tree: 5 levels, one cascade per WARP ----
    #pragma unroll 1
    for (int L = 0; L < 5; L++) {
        int npairs = 16 >> L;
        if (lane == 0 && wrp < npairs) {
            int seg = 64 << L;
            int ls  = wrp * seg;
            cascade(bA, jl, jr, ls, ls + (seg >> 1), ls + seg);
        }
        __syncthreads();
    }

    // ---- fill-forward: valid slot index max-scan gives each position its block start ----
    float2 bme = bA[tid];
    int mp = (bme.y > 0.0f) ? tid : -1;
    #pragma unroll
    for (int o = 1; o < 32; o <<= 1) {
        int t = __shfl_up_sync(FULL, mp, o);
        if (lane >= o) mp = max(mp, t);
    }
    if (lane == 31) part_b[wrp] = mp;
    __syncthreads();
    if (tid < 32) {
        int p = part_b[tid];
        #pragma unroll
        for (int o = 1; o < 32; o <<= 1) {
            int t = __shfl_up_sync(FULL, p, o);
            if (tid >= o) p = max(p, t);
        }
        part_b[tid] = p;
    }
    __syncthreads();
    if (wrp > 0) mp = max(mp, part_b[wrp - 1]);

    float2 blk = bA[mp];                       // block containing position tid
    float y = fmaxf(blk.x / blk.y, 0.0f);      // pooled mean, clamped; nonincreasing in tid
    float z = sgn_i * y;                       // oscar prox at sorted position tid

    // ---- fused epilogue: one combined scan -> rank AND sorted cumsum ----
    {
        int fP = (z > 0.0f) ? 1 : 0;
        int fN = (z < 0.0f) ? 1 : 0;
        int   pk = (fP << 16) | fN;
        float zp = fP ? z : 0.0f;
        float zn = fN ? z : 0.0f;
        int   ipk = pk;
        float izp = zp, izn = zn;
        #pragma unroll
        for (int o = 1; o < 32; o <<= 1) {
            int   ti = __shfl_up_sync(FULL, ipk, o);
            float tp = __shfl_up_sync(FULL, izp, o);
            float tn = __shfl_up_sync(FULL, izn, o);
            if (lane >= o) { ipk += ti; izp += tp; izn += tn; }
        }
        if (lane == 31) { part_c[wrp] = ipk; part_p[wrp] = izp; part_n[wrp] = izn; }
        __syncthreads();
        if (tid < 32) {
            int   p  = part_c[tid];
            float pp = part_p[tid];
            float pn = part_n[tid];
            #pragma unroll
            for (int o = 1; o < 32; o <<= 1) {
                int   ti = __shfl_up_sync(FULL, p,  o);
                float tp = __shfl_up_sync(FULL, pp, o);
                float tn = __shfl_up_sync(FULL, pn, o);
                if (tid >= o) { p += ti; pp += tp; pn += tn; }
            }
            part_c[tid] = p; part_p[tid] = pp; part_n[tid] = pn;
        }
        __syncthreads();
        if (wrp > 0) {
            ipk += part_c[wrp - 1];
            izp += part_p[wrp - 1];
            izn += part_n[wrp - 1];
        }
        int   total = part_c[31];
        float totP  = part_p[31];
        float totN  = part_n[31];

        int excl = ipk - pk;
        int pPex = excl >> 16;
        int pNex = excl & 0xffff;
        int totalPcnt = total >> 16;

        int pos;
        float c;
        if (z > 0.0f)      { pos = pPex;                            c = izp; }
        else if (z < 0.0f) { pos = DD - 1 - pNex;                   c = (totP + totN) - (izn - zn); }
        else               { pos = totalPcnt + (tid - pPex - pNex); c = totP; }

        bool flag = (1.0f + (float)(pos + 1) * z) > c;
        int k_sup = __syncthreads_count(flag);        // support is a prefix in sorted order
        if (pos == k_sup - 1) tau_sh = (c - 1.0f) / (float)k_sup;
        __syncthreads();

        out[row * DD + idx] = fmaxf(z - tau_sh, 0.0f);
    }
}

extern "C" void kernel_launch(void* const* d_in, const int* in_sizes, int n_in,
                              void* d_out, int out_size) {
    const float* x = (const float*)d_in[0];
    float* out = (float*)d_out;
    oscarmax_kernel<<<BB, DD>>>(x, out);
}

// round 12
// speedup vs baseline: 1.4932x; 1.2583x over previous
#include <cuda_runtime.h>

typedef unsigned long long u64;
typedef unsigned int u32;

#define DD 1024
#define BB 64
#define BETA_W 0.001f

// Junction cascade over a gapped, position-indexed block array with edge pointers.
__device__ void cascade(float2* b, int* jl, int* jr, int ls, int junc, int re) {
    int li = junc - 1;
    float2 L = b[li];
    if (L.y == 0.0f) { li = jl[li]; L = b[li]; }
    float2 P = b[junc];
    if (!(L.x * P.y < P.x * L.y)) return;
    P.x += L.x; P.y += L.y;
    b[li].y = 0.0f;
    b[junc].y = 0.0f;
    int lpos = li;
    int lc = li - 1;
    int rc = junc + 1;
    int lstop = ls - 1;
    int rstop = re;
    bool changed = true;
    while (changed) {
        changed = false;
        while (lc >= ls) {
            float2 Lb = b[lc];
            if (Lb.y == 0.0f) { lc = jl[lc]; if (lc < ls) break; Lb = b[lc]; }
            if (Lb.x * P.y < P.x * Lb.y) {
                P.x += Lb.x; P.y += Lb.y;
                b[lc].y = 0.0f;
                lpos = lc; --lc; changed = true;
            } else { lstop = lc; break; }
        }
        while (rc < re) {
            float2 Rb = b[rc];
            if (Rb.y == 0.0f) { rc = jr[rc]; if (rc >= re) break; Rb = b[rc]; }
            if (Rb.x * P.y > P.x * Rb.y) {
                P.x += Rb.x; P.y += Rb.y;
                b[rc].y = 0.0f;
                ++rc; changed = true;
            } else { rstop = rc; break; }
        }
    }
    b[lpos] = P;
    if (lpos - 1 > lstop) { jl[lpos - 1] = lstop; jr[lstop + 1] = lpos; }
    if (rstop - 1 > lpos) { jl[rstop - 1] = lpos; jr[lpos + 1] = rstop; }
}

__global__ __launch_bounds__(1024) void oscarmax_kernel(const float* __restrict__ x,
                                                        float* __restrict__ out) {
    __shared__ u64   sbuf[2][DD];      // scatter buf / sorted buf; after: bA | jl/jr
    __shared__ int   cnt[DD];          // bucket sizes
    __shared__ int   basx[DD];         // bucket start (exclusive scan)
    __shared__ int   offs[DD];         // running scatter offsets
    __shared__ int   part_b[32];       // fill max-scan
    __shared__ int   part_c[32];       // bucket scan + rank scan (barrier-separated)
    __shared__ float part_p[32];       // positive-sum scan
    __shared__ float part_n[32];       // negative-sum scan
    __shared__ float tau_sh;

    float2* bA = (float2*)&sbuf[0][0];
    int*    jl = (int*)&sbuf[1][0];
    int*    jr = jl + DD;
    u64*    s64a = &sbuf[0][0];        // scattered (unordered within bucket)
    u64*    s64b = &sbuf[1][0];        // fully sorted

    const int tid  = threadIdx.x;
    const int lane = tid & 31;
    const int wrp  = tid >> 5;
    const int row  = blockIdx.x;
    const unsigned FULL = 0xffffffffu;

    // ---- load, pack sortable u64: key=|x| bits (desc), payload=(idx<<1)|negbit ----
    float xv = x[row * DD + tid];
    float ax = fabsf(xv);
    u32 kb = __float_as_uint(ax);
    u32 pl = ((u32)tid << 1) | (xv < 0.0f ? 1u : 0u);
    u64 v = ((u64)kb << 32) | pl;

    // ---- bucket sort (descending): monotone bucket, exact in-bucket ranking ----
    int bkt = 1023 - min(1023, (int)(ax * 256.0f));   // descending bucket order
    cnt[tid] = 0;
    __syncthreads();
    atomicAdd(&cnt[bkt], 1);
    __syncthreads();

    // exclusive scan of cnt -> basx (and offs copy for scatter atomics)
    {
        int csz = cnt[tid];
        int inc = csz;
        #pragma unroll
        for (int o = 1; o < 32; o <<= 1) {
            int t = __shfl_up_sync(FULL, inc, o);
            if (lane >= o) inc += t;
        }
        if (lane == 31) part_c[wrp] = inc;
        __syncthreads();
        if (tid < 32) {
            int p = part_c[tid];
            #pragma unroll
            for (int o = 1; o < 32; o <<= 1) {
                int t = __shfl_up_sync(FULL, p, o);
                if (tid >= o) p += t;
            }
            part_c[tid] = p;
        }
        __syncthreads();
        if (wrp > 0) inc += part_c[wrp - 1];
        int excl = inc - csz;
        basx[tid] = excl;
        offs[tid] = excl;
    }
    __syncthreads();

    // scatter into bucket region (unordered within bucket)
    {
        int slot = atomicAdd(&offs[bkt], 1);
        s64a[slot] = v;
    }
    __syncthreads();

    // exact within-bucket rank (descending): r = #{peer > v}; place at basx+r
    {
        int st = basx[bkt];
        int sz = cnt[bkt];
        int r = 0;
        #pragma unroll 1
        for (int q = 0; q < sz; q++) {
            u64 u = s64a[st + q];
            r += (u > v) ? 1 : 0;
        }
        s64b[st + r] = v;
    }
    __syncthreads();
    v = s64b[tid];      // fully sorted descending, strict total order -> deterministic

    // ---- unpack: key, index, sign all from the sorted word ----
    float keyf  = __uint_as_float((u32)(v >> 32));
    u32   plo   = (u32)v;
    int   idx   = (int)(plo >> 1);
    float sgn_i = (plo & 1u) ? -1.0f : 1.0f;
    float sval  = keyf - BETA_W * (float)(DD - 1 - tid);
    __syncthreads();     // all sorted reads done; sbuf dead -> bA / jl / jr

    // ---- per-chunk PAVA: register stack (lane-indexed, shfl-accessed), lockstep ----
    {
        const int base = wrp << 5;
        bA[base + lane] = make_float2(0.0f, 0.0f);      // clear chunk slots
        __syncwarp();

        float psum = 0.0f, pcnt = 0.0f;                 // stack entry owned by this lane
        int   ppos = 0;
        int nb = 0;
        float ts = __shfl_sync(FULL, sval, 0), tc = 1.0f;
        int tpos = 0;
        #pragma unroll 1
        for (int i = 1; i < 32; i++) {
            float cs = __shfl_sync(FULL, sval, i), cc = 1.0f;
            int cpos = i;
            for (;;) {
                if (cs * tc > ts * cc) {                // cur_mean > top_mean: pool
                    cs += ts; cc += tc; cpos = tpos;
                    if (nb > 0) {
                        --nb;
                        ts   = __shfl_sync(FULL, psum, nb);
                        tc   = __shfl_sync(FULL, pcnt, nb);
                        tpos = __shfl_sync(FULL, ppos, nb);
                    } else { ts = cs; tc = cc; tpos = cpos; goto nexti; }
                } else break;
            }
            if (lane == nb) { psum = ts; pcnt = tc; ppos = tpos; }
            nb++;
            ts = cs; tc = cc; tpos = cpos;
            nexti: ;
        }
        if (lane == nb) { psum = ts; pcnt = tc; ppos = tpos; }
        nb++;

        if (lane < nb) {
            int st = base + ppos;
            int c  = (int)pcnt;
            bA[st] = make_float2(psum, pcnt);
            if (c > 1) {
                jr[st + 1]     = st + c;
                jl[st + c - 1] = st;
            }
        }
    }
    __syncthreads();     // bA, jl/jr visible

    // ---- merge tree: 5 levels, one cascade per WARP ----
    #pragma unroll 1
    for (int L = 0; L < 5; L++) {
        int npairs = 16 >> L;
        if (lane == 0 && wrp < npairs) {
            int seg = 64 << L;
            int ls  = wrp * seg;
            cascade(bA, jl, jr, ls, ls + (seg >> 1), ls + seg);
        }
        __syncthreads();
    }

    // ---- fill-forward: valid slot index max-scan gives each position its block start ----
    float2 bme = bA[tid];
    int mp = (bme.y > 0.0f) ? tid : -1;
    #pragma unroll
    for (int o = 1; o < 32; o <<= 1) {
        int t = __shfl_up_sync(FULL, mp, o);
        if (lane >= o) mp = max(mp, t);
    }
    if (lane == 31) part_b[wrp] = mp;
    __syncthreads();
    if (tid < 32) {
        int p = part_b[tid];
        #pragma unroll
        for (int o = 1; o < 32; o <<= 1) {
            int t = __shfl_up_sync(FULL, p, o);
            if (tid >= o) p = max(p, t);
        }
        part_b[tid] = p;
    }
    __syncthreads();
    if (wrp > 0) mp = max(mp, part_b[wrp - 1]);

    float2 blk = bA[mp];                       // block containing position tid
    float y = fmaxf(blk.x / blk.y, 0.0f);      // pooled mean, clamped; nonincreasing in tid
    float z = sgn_i * y;                       // oscar prox at sorted position tid

    // ---- fused epilogue: one combined scan -> rank AND sorted cumsum ----
    {
        int fP = (z > 0.0f) ? 1 : 0;
        int fN = (z < 0.0f) ? 1 : 0;
        int   pk = (fP << 16) | fN;
        float zp = fP ? z : 0.0f;
        float zn = fN ? z : 0.0f;
        int   ipk = pk;
        float izp = zp, izn = zn;
        #pragma unroll
        for (int o = 1; o < 32; o <<= 1) {
            int   ti = __shfl_up_sync(FULL, ipk, o);
            float tp = __shfl_up_sync(FULL, izp, o);
            float tn = __shfl_up_sync(FULL, izn, o);
            if (lane >= o) { ipk += ti; izp += tp; izn += tn; }
        }
        if (lane == 31) { part_c[wrp] = ipk; part_p[wrp] = izp; part_n[wrp] = izn; }
        __syncthreads();
        if (tid < 32) {
            int   p  = part_c[tid];
            float pp = part_p[tid];
            float pn = part_n[tid];
            #pragma unroll
            for (int o = 1; o < 32; o <<= 1) {
                int   ti = __shfl_up_sync(FULL, p,  o);
                float tp = __shfl_up_sync(FULL, pp, o);
                float tn = __shfl_up_sync(FULL, pn, o);
                if (tid >= o) { p += ti; pp += tp; pn += tn; }
            }
            part_c[tid] = p; part_p[tid] = pp; part_n[tid] = pn;
        }
        __syncthreads();
        if (wrp > 0) {
            ipk += part_c[wrp - 1];
            izp += part_p[wrp - 1];
            izn += part_n[wrp - 1];
        }
        int   total = part_c[31];
        float totP  = part_p[31];
        float totN  = part_n[31];

        int excl = ipk - pk;
        int pPex = excl >> 16;
        int pNex = excl & 0xffff;
        int totalPcnt = total >> 16;

        int pos;
        float c;
        if (z > 0.0f)      { pos = pPex;                            c = izp; }
        else if (z < 0.0f) { pos = DD - 1 - pNex;                   c = (totP + totN) - (izn - zn); }
        else               { pos = totalPcnt + (tid - pPex - pNex); c = totP; }

        bool flag = (1.0f + (float)(pos + 1) * z) > c;
        int k_sup = __syncthreads_count(flag);        // support is a prefix in sorted order
        if (pos == k_sup - 1) tau_sh = (c - 1.0f) / (float)k_sup;
        __syncthreads();

        out[row * DD + idx] = fmaxf(z - tau_sh, 0.0f);
    }
}

extern "C" void kernel_launch(void* const* d_in, const int* in_sizes, int n_in,
                              void* d_out, int out_size) {
    const float* x = (const float*)d_in[0];
    float* out = (float*)d_out;
    oscarmax_kernel<<<BB, DD>>>(x, out);
}